// round 2
// baseline (speedup 1.0000x reference)
#include <cuda_runtime.h>
#include <math.h>

// Problem constants
#define NN 4096
#define HH 128
#define EE 131072

// ---------------- scratch (static device arrays; no allocation) ----------------
__device__ float g_Y[NN * HH];
__device__ float g_h1[NN * HH];
__device__ float g_h2[NN * HH];
__device__ float g_z1[NN * HH];
__device__ float g_z3[NN * HH];
__device__ float g_mix[2 * NN * HH];      // stacked MHA-mix input [2,N,H]
__device__ float g_fus[2 * NN * HH];      // stacked MHA-fus input [2,N,H] (h3_c1 | h3_c2)
__device__ float g_qkv[2 * NN * 3 * HH];  // [2,N,384]
__device__ float g_obar[NN * HH];
__device__ float g_h1mix[NN * HH];
__device__ float g_TqkvM[3 * HH * HH];
__device__ float g_ToM[HH * HH];
__device__ float g_TqkvF[3 * HH * HH];
__device__ float g_ToF[HH * HH];

// ---------------- generic SGEMM: C[M,ncols] = A[M,K] @ B[K,ncols] + epilogue ----
// BM=32 rows per CTA, 128-col tile per blockIdx.y, BK=32. 256 threads,
// 4x4 register tile per thread. Assumes M%32==0, K%32==0, ncols%128==0,
// all pointers 16B-aligned (true for every call here).
#define BM 32
#define BK 32

__global__ __launch_bounds__(256) void sgemm_kernel(
    const float* __restrict__ A, const float* __restrict__ B,
    float* __restrict__ C, int M, int K, int ncols,
    const float* __restrict__ bias, const float* __restrict__ resid,
    int do_relu, const float* __restrict__ scale_ptr)
{
    __shared__ float As[BK][BM];    // transposed A tile
    __shared__ float Bs[BK][128];

    const int tid = threadIdx.x;
    const int tx = tid & 31;        // col group
    const int ty = tid >> 5;        // row group (0..7)
    const int row0 = blockIdx.x * BM;
    const int col0 = blockIdx.y * 128;

    float acc[4][4];
#pragma unroll
    for (int i = 0; i < 4; i++)
#pragma unroll
        for (int j = 0; j < 4; j++) acc[i][j] = 0.0f;

    const int a_row = tid >> 3;          // 0..31
    const int a_k4  = (tid & 7) * 4;     // 0,4,...,28
    const int b_c4  = (tid & 31) * 4;    // 0..124
    const int b_kr  = tid >> 5;          // 0..7

    for (int kt = 0; kt < K; kt += BK) {
        // load A tile (transposed into As[k][row])
        float4 a = *(const float4*)(A + (size_t)(row0 + a_row) * K + kt + a_k4);
        As[a_k4 + 0][a_row] = a.x;
        As[a_k4 + 1][a_row] = a.y;
        As[a_k4 + 2][a_row] = a.z;
        As[a_k4 + 3][a_row] = a.w;
        // load B tile
#pragma unroll
        for (int i = 0; i < 4; i++) {
            int kr = b_kr + i * 8;
            *(float4*)(&Bs[kr][b_c4]) =
                *(const float4*)(B + (size_t)(kt + kr) * ncols + col0 + b_c4);
        }
        __syncthreads();

#pragma unroll
        for (int k = 0; k < BK; k++) {
            float4 av = *(const float4*)(&As[k][ty * 4]);
            float4 bv = *(const float4*)(&Bs[k][tx * 4]);
            float ar[4] = {av.x, av.y, av.z, av.w};
            float br[4] = {bv.x, bv.y, bv.z, bv.w};
#pragma unroll
            for (int i = 0; i < 4; i++)
#pragma unroll
                for (int j = 0; j < 4; j++)
                    acc[i][j] = fmaf(ar[i], br[j], acc[i][j]);
        }
        __syncthreads();
    }

    const float scale = scale_ptr ? *scale_ptr : 1.0f;
#pragma unroll
    for (int i = 0; i < 4; i++) {
        const int r = row0 + ty * 4 + i;
        float4 outv;
        float* o = (float*)&outv;
#pragma unroll
        for (int j = 0; j < 4; j++) {
            const int c = col0 + tx * 4 + j;
            float v = acc[i][j];
            if (bias)  v += bias[c];
            if (resid) v += resid[(size_t)r * ncols + c];
            if (do_relu) v = fmaxf(v, 0.0f);
            o[j] = v * scale;
        }
        *(float4*)(C + (size_t)r * ncols + col0 + tx * 4) = outv;
    }
}

// ---------------- transpose: out[C,R] = in[R,C]^T ------------------------------
__global__ void transpose_kernel(const float* __restrict__ in, float* __restrict__ out,
                                 int R, int C)
{
    int i = blockIdx.x * blockDim.x + threadIdx.x;
    if (i >= R * C) return;
    int r = i / C, c = i - r * C;
    out[c * R + r] = in[i];
}

// ---------------- mixup combine: stack[l] = lam*z + (1-lam)*z[perm] -----------
__global__ void mixcombine_kernel(const float* __restrict__ z1,
                                  const float* __restrict__ z3,
                                  const int* __restrict__ perm,
                                  const float* __restrict__ lam,
                                  float* __restrict__ stack)
{
    int i = blockIdx.x * blockDim.x + threadIdx.x;
    if (i >= NN * HH) return;
    int b = i >> 7;
    int t = i & 127;
    float l = lam[0];
    int pb = perm[b];
    stack[i]           = l * z1[i] + (1.0f - l) * z1[pb * HH + t];
    stack[NN * HH + i] = l * z3[i] + (1.0f - l) * z3[pb * HH + t];
}

// ---------------- L=2 self-attention, per (node, head) thread ------------------
// qkv: [2, N, 384] (q|k|v each 128). Writes obar[b, h*hd + t] = mean_l attention out.
__global__ void attn_kernel(const float* __restrict__ qkv, float* __restrict__ obar,
                            int nh)
{
    int idx = blockIdx.x * blockDim.x + threadIdx.x;
    if (idx >= NN * nh) return;
    int b = idx / nh;
    int h = idx - b * nh;
    int hd = HH / nh;

    const float* base0 = qkv + (size_t)b * 384;
    const float* base1 = qkv + (size_t)NN * 384 + (size_t)b * 384;
    const float* q0 = base0 + h * hd;
    const float* k0 = base0 + 128 + h * hd;
    const float* v0 = base0 + 256 + h * hd;
    const float* q1 = base1 + h * hd;
    const float* k1 = base1 + 128 + h * hd;
    const float* v1 = base1 + 256 + h * hd;

    float s00 = 0.f, s01 = 0.f, s10 = 0.f, s11 = 0.f;
    for (int t = 0; t < hd; t++) {
        float a = q0[t], bq = q1[t], c = k0[t], d = k1[t];
        s00 = fmaf(a, c, s00);
        s01 = fmaf(a, d, s01);
        s10 = fmaf(bq, c, s10);
        s11 = fmaf(bq, d, s11);
    }
    float inv = rsqrtf((float)hd);
    s00 *= inv; s01 *= inv; s10 *= inv; s11 *= inv;

    float m0 = fmaxf(s00, s01);
    float e00 = expf(s00 - m0), e01 = expf(s01 - m0);
    float d0 = e00 + e01;
    float m1 = fmaxf(s10, s11);
    float e10 = expf(s10 - m1), e11 = expf(s11 - m1);
    float d1 = e10 + e11;

    float w0 = 0.5f * (e00 / d0 + e10 / d1);
    float w1 = 0.5f * (e01 / d0 + e11 / d1);

    float* ob = obar + (size_t)b * HH + h * hd;
    for (int t = 0; t < hd; t++)
        ob[t] = w0 * v0[t] + w1 * v1[t];
}

// ---------------- edge head: warp per edge -------------------------------------
// out[e, :] = concat(h3[src], h3[dst]) @ Wc[256,2] + bc
__global__ __launch_bounds__(256) void edge_kernel(
    const float* __restrict__ h3, const int* __restrict__ ei,
    const float* __restrict__ Wc, const float* __restrict__ bc,
    float* __restrict__ out)
{
    __shared__ float sWc[512];
    __shared__ float sbc[2];
    for (int i = threadIdx.x; i < 512; i += blockDim.x) sWc[i] = Wc[i];
    if (threadIdx.x < 2) sbc[threadIdx.x] = bc[threadIdx.x];
    __syncthreads();

    int warp = (blockIdx.x * blockDim.x + threadIdx.x) >> 5;
    int lane = threadIdx.x & 31;
    if (warp >= EE) return;

    int src = ei[warp];
    int dst = ei[EE + warp];
    float4 hs = *(const float4*)(h3 + (size_t)src * HH + lane * 4);
    float4 hd4 = *(const float4*)(h3 + (size_t)dst * HH + lane * 4);
    const float* hsp = (const float*)&hs;
    const float* hdp = (const float*)&hd4;

    float a0 = 0.f, a1 = 0.f;
#pragma unroll
    for (int i = 0; i < 4; i++) {
        int rs = lane * 4 + i;
        a0 = fmaf(hsp[i], sWc[rs * 2 + 0], a0);
        a0 = fmaf(hdp[i], sWc[(128 + rs) * 2 + 0], a0);
        a1 = fmaf(hsp[i], sWc[rs * 2 + 1], a1);
        a1 = fmaf(hdp[i], sWc[(128 + rs) * 2 + 1], a1);
    }
#pragma unroll
    for (int off = 16; off; off >>= 1) {
        a0 += __shfl_xor_sync(0xffffffffu, a0, off);
        a1 += __shfl_xor_sync(0xffffffffu, a1, off);
    }
    if (lane == 0) {
        out[(size_t)warp * 2 + 0] = a0 + sbc[0];
        out[(size_t)warp * 2 + 1] = a1 + sbc[1];
    }
}

// ---------------- host orchestration -------------------------------------------
static inline void sgemm(const float* A, const float* B, float* C,
                         int M, int K, int ncols,
                         const float* bias, const float* resid,
                         int relu, const float* scale)
{
    dim3 grid(M / BM, ncols / 128);
    sgemm_kernel<<<grid, 256>>>(A, B, C, M, K, ncols, bias, resid, relu, scale);
}

extern "C" void kernel_launch(void* const* d_in, const int* in_sizes, int n_in,
                              void* d_out, int out_size)
{
    const float* x     = (const float*)d_in[0];
    const float* G1    = (const float*)d_in[1];
    const float* G3    = (const float*)d_in[2];
    const int*   ei    = (const int*)d_in[3];
    const int*   perm  = (const int*)d_in[4];
    const float* lam   = (const float*)d_in[5];
    const float* beta  = (const float*)d_in[6];
    const float* W1    = (const float*)d_in[7];  const float* b1   = (const float*)d_in[8];
    const float* W2    = (const float*)d_in[9];  const float* b2   = (const float*)d_in[10];
    const float* W3    = (const float*)d_in[11]; const float* b3   = (const float*)d_in[12];
    const float* W1h   = (const float*)d_in[13]; const float* b1h  = (const float*)d_in[14];
    const float* W3h   = (const float*)d_in[15]; const float* b3h  = (const float*)d_in[16];
    const float* W2m   = (const float*)d_in[17]; const float* b2m  = (const float*)d_in[18];
    const float* W3m   = (const float*)d_in[19]; const float* b3m  = (const float*)d_in[20];
    const float* WqkvM = (const float*)d_in[21]; const float* bqkvM= (const float*)d_in[22];
    const float* WoM   = (const float*)d_in[23]; const float* boM  = (const float*)d_in[24];
    const float* WqkvF = (const float*)d_in[25]; const float* bqkvF= (const float*)d_in[26];
    const float* WoF   = (const float*)d_in[27]; const float* boF  = (const float*)d_in[28];
    const float* Wc    = (const float*)d_in[29]; const float* bc   = (const float*)d_in[30];

    float *Y, *h1, *h2, *z1, *z3, *mix, *fus, *qkv, *obar, *h1mix;
    float *TqkvM, *ToM, *TqkvF, *ToF;
    cudaGetSymbolAddress((void**)&Y,     g_Y);
    cudaGetSymbolAddress((void**)&h1,    g_h1);
    cudaGetSymbolAddress((void**)&h2,    g_h2);
    cudaGetSymbolAddress((void**)&z1,    g_z1);
    cudaGetSymbolAddress((void**)&z3,    g_z3);
    cudaGetSymbolAddress((void**)&mix,   g_mix);
    cudaGetSymbolAddress((void**)&fus,   g_fus);
    cudaGetSymbolAddress((void**)&qkv,   g_qkv);
    cudaGetSymbolAddress((void**)&obar,  g_obar);
    cudaGetSymbolAddress((void**)&h1mix, g_h1mix);
    cudaGetSymbolAddress((void**)&TqkvM, g_TqkvM);
    cudaGetSymbolAddress((void**)&ToM,   g_ToM);
    cudaGetSymbolAddress((void**)&TqkvF, g_TqkvF);
    cudaGetSymbolAddress((void**)&ToF,   g_ToF);

    float* out = (float*)d_out;
    float* h3  = out + (size_t)EE * 2;   // h3 region of the output

    // weight transposes (x @ W^T layouts)
    transpose_kernel<<<(3 * HH * HH + 255) / 256, 256>>>(WqkvM, TqkvM, 3 * HH, HH);
    transpose_kernel<<<(HH * HH + 255) / 256, 256>>>(WoM, ToM, HH, HH);
    transpose_kernel<<<(3 * HH * HH + 255) / 256, 256>>>(WqkvF, TqkvF, 3 * HH, HH);
    transpose_kernel<<<(HH * HH + 255) / 256, 256>>>(WoF, ToF, HH, HH);

    // h1 = relu(G1 @ (x W1 + b1))
    sgemm(x, W1, Y, NN, HH, HH, b1, nullptr, 0, nullptr);
    sgemm(G1, Y, h1, NN, NN, HH, nullptr, nullptr, 1, nullptr);
    // h2 = relu(G1 @ (h1 W2 + b2) + h1)
    sgemm(h1, W2, Y, NN, HH, HH, b2, nullptr, 0, nullptr);
    sgemm(G1, Y, h2, NN, NN, HH, nullptr, h1, 1, nullptr);
    // h3_c1 = relu(G1 @ (h2 W3 + b3) + h2)  -> fus[0]
    sgemm(h2, W3, Y, NN, HH, HH, b3, nullptr, 0, nullptr);
    sgemm(G1, Y, fus, NN, NN, HH, nullptr, h2, 1, nullptr);
    // z1 = G1 @ (h1 W1h + b1h);  z3 = G3 @ (h1 W3h + b3h)
    sgemm(h1, W1h, Y, NN, HH, HH, b1h, nullptr, 0, nullptr);
    sgemm(G1, Y, z1, NN, NN, HH, nullptr, nullptr, 0, nullptr);
    sgemm(h1, W3h, Y, NN, HH, HH, b3h, nullptr, 0, nullptr);
    sgemm(G3, Y, z3, NN, NN, HH, nullptr, nullptr, 0, nullptr);
    // mixup (permuted-graph term == z[perm], algebraic identity)
    mixcombine_kernel<<<(NN * HH + 255) / 256, 256>>>(z1, z3, perm, lam, mix);
    // MHA mix (nh=2), mean folded before output projection
    sgemm(mix, TqkvM, qkv, 2 * NN, HH, 3 * HH, bqkvM, nullptr, 0, nullptr);
    attn_kernel<<<(NN * 2 + 255) / 256, 256>>>(qkv, obar, 2);
    sgemm(obar, ToM, h1mix, NN, HH, HH, boM, nullptr, 0, nullptr);
    // h2_mix = relu(G1 @ (h1mix W2m + b2m) + h1mix)
    sgemm(h1mix, W2m, Y, NN, HH, HH, b2m, nullptr, 0, nullptr);
    sgemm(G1, Y, h2, NN, NN, HH, nullptr, h1mix, 1, nullptr);
    // h3_c2 = relu(G1 @ (h2mix W3m + b3m) + h2mix) * beta  -> fus[1]
    sgemm(h2, W3m, Y, NN, HH, HH, b3m, nullptr, 0, nullptr);
    sgemm(G1, Y, fus + (size_t)NN * HH, NN, NN, HH, nullptr, h2, 1, beta);
    // MHA fus (nh=4); h3 written directly into d_out tail
    sgemm(fus, TqkvF, qkv, 2 * NN, HH, 3 * HH, bqkvF, nullptr, 0, nullptr);
    attn_kernel<<<(NN * 4 + 255) / 256, 256>>>(qkv, obar, 4);
    sgemm(obar, ToF, h3, NN, HH, HH, boF, nullptr, 0, nullptr);
    // edge predictions
    edge_kernel<<<EE / 8, 256>>>(h3, ei, Wc, bc, out);
}

// round 3
// speedup vs baseline: 2.5081x; 2.5081x over previous
#include <cuda_runtime.h>
#include <cuda_bf16.h>
#include <math.h>

// Problem constants
#define NN 4096
#define HH 128
#define EE 131072

// ---------------- scratch (static device arrays; no allocation) ----------------
__device__ float g_Y[NN * HH];
__device__ float g_h1[NN * HH];
__device__ float g_h2[NN * HH];
__device__ float g_z1[NN * HH];
__device__ float g_z3[NN * HH];
__device__ float g_mix[2 * NN * HH];
__device__ float g_fus[2 * NN * HH];
__device__ float g_qkv[2 * NN * 3 * HH];
__device__ float g_obar[NN * HH];
__device__ float g_h1mix[NN * HH];
__device__ float g_ToM[HH * HH];
__device__ float g_ToF[HH * HH];
__device__ float g_part[4 * NN * HH];                 // split-K partials
__device__ __nv_bfloat16 g_BtYh[HH * NN];             // B^T hi  [Nc=128][K=4096]
__device__ __nv_bfloat16 g_BtYl[HH * NN];             // B^T lo
__device__ __nv_bfloat16 g_BtWh[3 * HH * HH];         // weight Bt hi (max 384x128)
__device__ __nv_bfloat16 g_BtWl[3 * HH * HH];

// =======================================================================
// Tensor-core GEMM: C[M,Nc] = A[M,K] @ B[K,Nc]
//   A fp32 row-major (split to bf16 hi/lo in-kernel)
//   B given pre-split & transposed: Bth/Btl bf16 [Nc][K] row-major
//   grid (M/128, Nc/128, KS). If KS>1: write partials at C + z*M*Nc (no bias).
//   Emulated fp32: Ahi*Bhi + Ahi*Blo + Alo*Bhi  (fp32 accumulate)
// =======================================================================
#define MMA_BF16(d, a0, a1, a2, a3, b0, b1)                                   \
    asm volatile(                                                             \
        "mma.sync.aligned.m16n8k16.row.col.f32.bf16.bf16.f32 "                \
        "{%0,%1,%2,%3}, {%4,%5,%6,%7}, {%8,%9}, {%0,%1,%2,%3};"               \
        : "+f"(d[0]), "+f"(d[1]), "+f"(d[2]), "+f"(d[3])                      \
        : "r"(a0), "r"(a1), "r"(a2), "r"(a3), "r"(b0), "r"(b1))

__global__ __launch_bounds__(256) void tgemm_kernel(
    const float* __restrict__ A,
    const __nv_bfloat16* __restrict__ Bth,
    const __nv_bfloat16* __restrict__ Btl,
    float* __restrict__ C, int M, int K, int Nc,
    const float* __restrict__ bias)
{
    __shared__ __nv_bfloat16 sAh[128][40];
    __shared__ __nv_bfloat16 sAl[128][40];
    __shared__ __nv_bfloat16 sBh[128][40];
    __shared__ __nv_bfloat16 sBl[128][40];

    const int tid  = threadIdx.x;
    const int row0 = blockIdx.x * 128;
    const int col0 = blockIdx.y * 128;
    const int KS     = gridDim.z;
    const int kiters = K / (32 * KS);
    const int kbase  = blockIdx.z * kiters * 32;

    const int warp = tid >> 5, lane = tid & 31;
    const int wm = warp & 3, wn = warp >> 2;          // 4 x 2 warp grid
    const int grp = lane >> 2, thr4 = lane & 3;

    float acc[2][8][4];
#pragma unroll
    for (int mf = 0; mf < 2; mf++)
#pragma unroll
        for (int nf = 0; nf < 8; nf++)
#pragma unroll
            for (int i = 0; i < 4; i++) acc[mf][nf][i] = 0.0f;

    float4 pa[4];
    uint4  pbh[2], pbl[2];

    // prefetch tile 0
    {
        const int kt = kbase;
#pragma unroll
        for (int i = 0; i < 4; i++) {
            int id = tid + i * 256, r = id >> 3, c = (id & 7) * 4;
            pa[i] = *(const float4*)(A + (size_t)(row0 + r) * K + kt + c);
        }
#pragma unroll
        for (int i = 0; i < 2; i++) {
            int id = tid + i * 256, r = id >> 2, q = (id & 3) * 8;
            pbh[i] = *(const uint4*)(Bth + (size_t)(col0 + r) * K + kt + q);
            pbl[i] = *(const uint4*)(Btl + (size_t)(col0 + r) * K + kt + q);
        }
    }

    for (int it = 0; it < kiters; it++) {
        // ---- store prefetched tile into smem (A split into hi/lo) ----
#pragma unroll
        for (int i = 0; i < 4; i++) {
            int id = tid + i * 256, r = id >> 3, c = (id & 7) * 4;
            float v[4] = {pa[i].x, pa[i].y, pa[i].z, pa[i].w};
            __nv_bfloat16 h[4], l[4];
#pragma unroll
            for (int j = 0; j < 4; j++) {
                h[j] = __float2bfloat16(v[j]);
                l[j] = __float2bfloat16(v[j] - __bfloat162float(h[j]));
            }
            *(__nv_bfloat162*)&sAh[r][c]     = __halves2bfloat162(h[0], h[1]);
            *(__nv_bfloat162*)&sAh[r][c + 2] = __halves2bfloat162(h[2], h[3]);
            *(__nv_bfloat162*)&sAl[r][c]     = __halves2bfloat162(l[0], l[1]);
            *(__nv_bfloat162*)&sAl[r][c + 2] = __halves2bfloat162(l[2], l[3]);
        }
#pragma unroll
        for (int i = 0; i < 2; i++) {
            int id = tid + i * 256, r = id >> 2, q = (id & 3) * 8;
            *(uint4*)&sBh[r][q] = pbh[i];
            *(uint4*)&sBl[r][q] = pbl[i];
        }
        __syncthreads();

        // ---- prefetch next tile ----
        if (it + 1 < kiters) {
            const int kt = kbase + (it + 1) * 32;
#pragma unroll
            for (int i = 0; i < 4; i++) {
                int id = tid + i * 256, r = id >> 3, c = (id & 7) * 4;
                pa[i] = *(const float4*)(A + (size_t)(row0 + r) * K + kt + c);
            }
#pragma unroll
            for (int i = 0; i < 2; i++) {
                int id = tid + i * 256, r = id >> 2, q = (id & 3) * 8;
                pbh[i] = *(const uint4*)(Bth + (size_t)(col0 + r) * K + kt + q);
                pbl[i] = *(const uint4*)(Btl + (size_t)(col0 + r) * K + kt + q);
            }
        }

        // ---- compute ----
#pragma unroll
        for (int koff = 0; koff < 32; koff += 16) {
            unsigned int ah[2][4], al[2][4];
            const int c0 = koff + thr4 * 2;
#pragma unroll
            for (int mf = 0; mf < 2; mf++) {
                const int mb = wm * 32 + mf * 16;
                ah[mf][0] = *(const unsigned int*)&sAh[mb + grp][c0];
                ah[mf][1] = *(const unsigned int*)&sAh[mb + grp + 8][c0];
                ah[mf][2] = *(const unsigned int*)&sAh[mb + grp][c0 + 8];
                ah[mf][3] = *(const unsigned int*)&sAh[mb + grp + 8][c0 + 8];
                al[mf][0] = *(const unsigned int*)&sAl[mb + grp][c0];
                al[mf][1] = *(const unsigned int*)&sAl[mb + grp + 8][c0];
                al[mf][2] = *(const unsigned int*)&sAl[mb + grp][c0 + 8];
                al[mf][3] = *(const unsigned int*)&sAl[mb + grp + 8][c0 + 8];
            }
#pragma unroll
            for (int nf = 0; nf < 8; nf++) {
                const int nb = wn * 64 + nf * 8;
                unsigned int bh0 = *(const unsigned int*)&sBh[nb + grp][c0];
                unsigned int bh1 = *(const unsigned int*)&sBh[nb + grp][c0 + 8];
                unsigned int bl0 = *(const unsigned int*)&sBl[nb + grp][c0];
                unsigned int bl1 = *(const unsigned int*)&sBl[nb + grp][c0 + 8];
#pragma unroll
                for (int mf = 0; mf < 2; mf++) {
                    MMA_BF16(acc[mf][nf], ah[mf][0], ah[mf][1], ah[mf][2], ah[mf][3], bh0, bh1);
                    MMA_BF16(acc[mf][nf], ah[mf][0], ah[mf][1], ah[mf][2], ah[mf][3], bl0, bl1);
                    MMA_BF16(acc[mf][nf], al[mf][0], al[mf][1], al[mf][2], al[mf][3], bh0, bh1);
                }
            }
        }
        __syncthreads();
    }

    // ---- epilogue ----
    float* Co = (KS > 1) ? C + (size_t)blockIdx.z * M * Nc : C;
#pragma unroll
    for (int mf = 0; mf < 2; mf++) {
        const int m = row0 + wm * 32 + mf * 16 + grp;
#pragma unroll
        for (int nf = 0; nf < 8; nf++) {
            const int n = col0 + wn * 64 + nf * 8 + thr4 * 2;
            float b0 = 0.f, b1 = 0.f;
            if (bias) { b0 = bias[n]; b1 = bias[n + 1]; }
            float2 v0 = make_float2(acc[mf][nf][0] + b0, acc[mf][nf][1] + b1);
            float2 v1 = make_float2(acc[mf][nf][2] + b0, acc[mf][nf][3] + b1);
            *(float2*)(Co + (size_t)m * Nc + n) = v0;
            *(float2*)(Co + (size_t)(m + 8) * Nc + n) = v1;
        }
    }
}

// ---------------- split-K reduce + epilogue (4 partials) ----------------------
__global__ void reduce4_kernel(const float* __restrict__ part, float* __restrict__ C,
                               const float* __restrict__ resid, int do_relu,
                               const float* __restrict__ scale_ptr)
{
    const int sz = NN * HH;
    int i = (blockIdx.x * blockDim.x + threadIdx.x) * 4;
    if (i >= sz) return;
    float4 a = *(const float4*)(part + i);
    float4 b = *(const float4*)(part + sz + i);
    float4 c = *(const float4*)(part + 2 * sz + i);
    float4 d = *(const float4*)(part + 3 * sz + i);
    float v[4] = {a.x + b.x + c.x + d.x, a.y + b.y + c.y + d.y,
                  a.z + b.z + c.z + d.z, a.w + b.w + c.w + d.w};
    if (resid) {
        float4 r = *(const float4*)(resid + i);
        v[0] += r.x; v[1] += r.y; v[2] += r.z; v[3] += r.w;
    }
    float s = scale_ptr ? *scale_ptr : 1.0f;
    float4 o;
    o.x = (do_relu ? fmaxf(v[0], 0.f) : v[0]) * s;
    o.y = (do_relu ? fmaxf(v[1], 0.f) : v[1]) * s;
    o.z = (do_relu ? fmaxf(v[2], 0.f) : v[2]) * s;
    o.w = (do_relu ? fmaxf(v[3], 0.f) : v[3]) * s;
    *(float4*)(C + i) = o;
}

// ---------------- transpose+split convert: Y[K,Nc] -> Bt hi/lo [Nc][K] --------
__global__ void convt_kernel(const float* __restrict__ Y,
                             __nv_bfloat16* __restrict__ Bth,
                             __nv_bfloat16* __restrict__ Btl, int K, int Nc)
{
    __shared__ float t[32][33];
    const int k0 = blockIdx.x * 32, n0 = blockIdx.y * 32;
    const int tx = threadIdx.x, ty = threadIdx.y;
#pragma unroll
    for (int i = 0; i < 4; i++)
        t[ty + i * 8][tx] = Y[(size_t)(k0 + ty + i * 8) * Nc + n0 + tx];
    __syncthreads();
#pragma unroll
    for (int i = 0; i < 4; i++) {
        int n = n0 + ty + i * 8, k = k0 + tx;
        float v = t[tx][ty + i * 8];
        __nv_bfloat16 h = __float2bfloat16(v);
        Bth[(size_t)n * K + k] = h;
        Btl[(size_t)n * K + k] = __float2bfloat16(v - __bfloat162float(h));
    }
}

// ---------------- no-transpose split convert (weights already [Nc][K]) --------
__global__ void convnt_kernel(const float* __restrict__ W,
                              __nv_bfloat16* __restrict__ h,
                              __nv_bfloat16* __restrict__ l, int sz)
{
    int i = blockIdx.x * blockDim.x + threadIdx.x;
    if (i >= sz) return;
    float v = W[i];
    __nv_bfloat16 hh = __float2bfloat16(v);
    h[i] = hh;
    l[i] = __float2bfloat16(v - __bfloat162float(hh));
}

// ---------------- FFMA SGEMM (kept for the small 128-K weight GEMMs) ----------
#define BM 32
#define BK 32

__global__ __launch_bounds__(256) void sgemm_kernel(
    const float* __restrict__ A, const float* __restrict__ B,
    float* __restrict__ C, int M, int K, int ncols,
    const float* __restrict__ bias, const float* __restrict__ resid,
    int do_relu, const float* __restrict__ scale_ptr)
{
    __shared__ float As[BK][BM];
    __shared__ float Bs[BK][128];

    const int tid = threadIdx.x;
    const int tx = tid & 31;
    const int ty = tid >> 5;
    const int row0 = blockIdx.x * BM;
    const int col0 = blockIdx.y * 128;

    float acc[4][4];
#pragma unroll
    for (int i = 0; i < 4; i++)
#pragma unroll
        for (int j = 0; j < 4; j++) acc[i][j] = 0.0f;

    const int a_row = tid >> 3;
    const int a_k4  = (tid & 7) * 4;
    const int b_c4  = (tid & 31) * 4;
    const int b_kr  = tid >> 5;

    for (int kt = 0; kt < K; kt += BK) {
        float4 a = *(const float4*)(A + (size_t)(row0 + a_row) * K + kt + a_k4);
        As[a_k4 + 0][a_row] = a.x;
        As[a_k4 + 1][a_row] = a.y;
        As[a_k4 + 2][a_row] = a.z;
        As[a_k4 + 3][a_row] = a.w;
#pragma unroll
        for (int i = 0; i < 4; i++) {
            int kr = b_kr + i * 8;
            *(float4*)(&Bs[kr][b_c4]) =
                *(const float4*)(B + (size_t)(kt + kr) * ncols + col0 + b_c4);
        }
        __syncthreads();
#pragma unroll
        for (int k = 0; k < BK; k++) {
            float4 av = *(const float4*)(&As[k][ty * 4]);
            float4 bv = *(const float4*)(&Bs[k][tx * 4]);
            float ar[4] = {av.x, av.y, av.z, av.w};
            float br[4] = {bv.x, bv.y, bv.z, bv.w};
#pragma unroll
            for (int i = 0; i < 4; i++)
#pragma unroll
                for (int j = 0; j < 4; j++)
                    acc[i][j] = fmaf(ar[i], br[j], acc[i][j]);
        }
        __syncthreads();
    }

    const float scale = scale_ptr ? *scale_ptr : 1.0f;
#pragma unroll
    for (int i = 0; i < 4; i++) {
        const int r = row0 + ty * 4 + i;
        float4 outv;
        float* o = (float*)&outv;
#pragma unroll
        for (int j = 0; j < 4; j++) {
            const int c = col0 + tx * 4 + j;
            float v = acc[i][j];
            if (bias)  v += bias[c];
            if (resid) v += resid[(size_t)r * ncols + c];
            if (do_relu) v = fmaxf(v, 0.0f);
            o[j] = v * scale;
        }
        *(float4*)(C + (size_t)r * ncols + col0 + tx * 4) = outv;
    }
}

// ---------------- transpose (for Wo only) --------------------------------------
__global__ void transpose_kernel(const float* __restrict__ in, float* __restrict__ out,
                                 int R, int C)
{
    int i = blockIdx.x * blockDim.x + threadIdx.x;
    if (i >= R * C) return;
    int r = i / C, c = i - r * C;
    out[c * R + r] = in[i];
}

// ---------------- mixup combine -------------------------------------------------
__global__ void mixcombine_kernel(const float* __restrict__ z1,
                                  const float* __restrict__ z3,
                                  const int* __restrict__ perm,
                                  const float* __restrict__ lam,
                                  float* __restrict__ stack)
{
    int i = blockIdx.x * blockDim.x + threadIdx.x;
    if (i >= NN * HH) return;
    int b = i >> 7;
    int t = i & 127;
    float l = lam[0];
    int pb = perm[b];
    stack[i]           = l * z1[i] + (1.0f - l) * z1[pb * HH + t];
    stack[NN * HH + i] = l * z3[i] + (1.0f - l) * z3[pb * HH + t];
}

// ---------------- L=2 self-attention -------------------------------------------
__global__ void attn_kernel(const float* __restrict__ qkv, float* __restrict__ obar,
                            int nh)
{
    int idx = blockIdx.x * blockDim.x + threadIdx.x;
    if (idx >= NN * nh) return;
    int b = idx / nh;
    int h = idx - b * nh;
    int hd = HH / nh;

    const float* base0 = qkv + (size_t)b * 384;
    const float* base1 = qkv + (size_t)NN * 384 + (size_t)b * 384;
    const float* q0 = base0 + h * hd;
    const float* k0 = base0 + 128 + h * hd;
    const float* v0 = base0 + 256 + h * hd;
    const float* q1 = base1 + h * hd;
    const float* k1 = base1 + 128 + h * hd;
    const float* v1 = base1 + 256 + h * hd;

    float s00 = 0.f, s01 = 0.f, s10 = 0.f, s11 = 0.f;
    for (int t = 0; t < hd; t++) {
        float a = q0[t], bq = q1[t], c = k0[t], d = k1[t];
        s00 = fmaf(a, c, s00);
        s01 = fmaf(a, d, s01);
        s10 = fmaf(bq, c, s10);
        s11 = fmaf(bq, d, s11);
    }
    float inv = rsqrtf((float)hd);
    s00 *= inv; s01 *= inv; s10 *= inv; s11 *= inv;

    float m0 = fmaxf(s00, s01);
    float e00 = expf(s00 - m0), e01 = expf(s01 - m0);
    float d0 = e00 + e01;
    float m1 = fmaxf(s10, s11);
    float e10 = expf(s10 - m1), e11 = expf(s11 - m1);
    float d1 = e10 + e11;

    float w0 = 0.5f * (e00 / d0 + e10 / d1);
    float w1 = 0.5f * (e01 / d0 + e11 / d1);

    float* ob = obar + (size_t)b * HH + h * hd;
    for (int t = 0; t < hd; t++)
        ob[t] = w0 * v0[t] + w1 * v1[t];
}

// ---------------- edge head ----------------------------------------------------
__global__ __launch_bounds__(256) void edge_kernel(
    const float* __restrict__ h3, const int* __restrict__ ei,
    const float* __restrict__ Wc, const float* __restrict__ bc,
    float* __restrict__ out)
{
    __shared__ float sWc[512];
    __shared__ float sbc[2];
    for (int i = threadIdx.x; i < 512; i += blockDim.x) sWc[i] = Wc[i];
    if (threadIdx.x < 2) sbc[threadIdx.x] = bc[threadIdx.x];
    __syncthreads();

    int warp = (blockIdx.x * blockDim.x + threadIdx.x) >> 5;
    int lane = threadIdx.x & 31;
    if (warp >= EE) return;

    int src = ei[warp];
    int dst = ei[EE + warp];
    float4 hs = *(const float4*)(h3 + (size_t)src * HH + lane * 4);
    float4 hd4 = *(const float4*)(h3 + (size_t)dst * HH + lane * 4);
    const float* hsp = (const float*)&hs;
    const float* hdp = (const float*)&hd4;

    float a0 = 0.f, a1 = 0.f;
#pragma unroll
    for (int i = 0; i < 4; i++) {
        int rs = lane * 4 + i;
        a0 = fmaf(hsp[i], sWc[rs * 2 + 0], a0);
        a0 = fmaf(hdp[i], sWc[(128 + rs) * 2 + 0], a0);
        a1 = fmaf(hsp[i], sWc[rs * 2 + 1], a1);
        a1 = fmaf(hdp[i], sWc[(128 + rs) * 2 + 1], a1);
    }
#pragma unroll
    for (int off = 16; off; off >>= 1) {
        a0 += __shfl_xor_sync(0xffffffffu, a0, off);
        a1 += __shfl_xor_sync(0xffffffffu, a1, off);
    }
    if (lane == 0) {
        out[(size_t)warp * 2 + 0] = a0 + sbc[0];
        out[(size_t)warp * 2 + 1] = a1 + sbc[1];
    }
}

// ---------------- host orchestration -------------------------------------------
static inline void sgemm(const float* A, const float* B, float* C,
                         int M, int K, int ncols,
                         const float* bias, const float* resid,
                         int relu, const float* scale)
{
    dim3 grid(M / BM, ncols / 128);
    sgemm_kernel<<<grid, 256>>>(A, B, C, M, K, ncols, bias, resid, relu, scale);
}

static inline void tgemm(const float* A, const __nv_bfloat16* Bh, const __nv_bfloat16* Bl,
                         float* C, int M, int K, int Nc, const float* bias, int KS)
{
    dim3 grid(M / 128, Nc / 128, KS);
    tgemm_kernel<<<grid, 256>>>(A, Bh, Bl, C, M, K, Nc, bias);
}

extern "C" void kernel_launch(void* const* d_in, const int* in_sizes, int n_in,
                              void* d_out, int out_size)
{
    const float* x     = (const float*)d_in[0];
    const float* G1    = (const float*)d_in[1];
    const float* G3    = (const float*)d_in[2];
    const int*   ei    = (const int*)d_in[3];
    const int*   perm  = (const int*)d_in[4];
    const float* lam   = (const float*)d_in[5];
    const float* beta  = (const float*)d_in[6];
    const float* W1    = (const float*)d_in[7];  const float* b1   = (const float*)d_in[8];
    const float* W2    = (const float*)d_in[9];  const float* b2   = (const float*)d_in[10];
    const float* W3    = (const float*)d_in[11]; const float* b3   = (const float*)d_in[12];
    const float* W1h   = (const float*)d_in[13]; const float* b1h  = (const float*)d_in[14];
    const float* W3h   = (const float*)d_in[15]; const float* b3h  = (const float*)d_in[16];
    const float* W2m   = (const float*)d_in[17]; const float* b2m  = (const float*)d_in[18];
    const float* W3m   = (const float*)d_in[19]; const float* b3m  = (const float*)d_in[20];
    const float* WqkvM = (const float*)d_in[21]; const float* bqkvM= (const float*)d_in[22];
    const float* WoM   = (const float*)d_in[23]; const float* boM  = (const float*)d_in[24];
    const float* WqkvF = (const float*)d_in[25]; const float* bqkvF= (const float*)d_in[26];
    const float* WoF   = (const float*)d_in[27]; const float* boF  = (const float*)d_in[28];
    const float* Wc    = (const float*)d_in[29]; const float* bc   = (const float*)d_in[30];

    float *Y, *h1, *h2, *z1, *z3, *mix, *fus, *qkv, *obar, *h1mix, *ToM, *ToF, *part;
    __nv_bfloat16 *BtYh, *BtYl, *BtWh, *BtWl;
    cudaGetSymbolAddress((void**)&Y,     g_Y);
    cudaGetSymbolAddress((void**)&h1,    g_h1);
    cudaGetSymbolAddress((void**)&h2,    g_h2);
    cudaGetSymbolAddress((void**)&z1,    g_z1);
    cudaGetSymbolAddress((void**)&z3,    g_z3);
    cudaGetSymbolAddress((void**)&mix,   g_mix);
    cudaGetSymbolAddress((void**)&fus,   g_fus);
    cudaGetSymbolAddress((void**)&qkv,   g_qkv);
    cudaGetSymbolAddress((void**)&obar,  g_obar);
    cudaGetSymbolAddress((void**)&h1mix, g_h1mix);
    cudaGetSymbolAddress((void**)&ToM,   g_ToM);
    cudaGetSymbolAddress((void**)&ToF,   g_ToF);
    cudaGetSymbolAddress((void**)&part,  g_part);
    cudaGetSymbolAddress((void**)&BtYh,  g_BtYh);
    cudaGetSymbolAddress((void**)&BtYl,  g_BtYl);
    cudaGetSymbolAddress((void**)&BtWh,  g_BtWh);
    cudaGetSymbolAddress((void**)&BtWl,  g_BtWl);

    float* out = (float*)d_out;
    float* h3  = out + (size_t)EE * 2;

    const dim3 cvt_grid(NN / 32, HH / 32), cvt_blk(32, 8);
    const int red_grid = (NN * HH / 4 + 255) / 256;

    // Wo transposes for the FFMA path
    transpose_kernel<<<(HH * HH + 255) / 256, 256>>>(WoM, ToM, HH, HH);
    transpose_kernel<<<(HH * HH + 255) / 256, 256>>>(WoF, ToF, HH, HH);

    // h1 = relu(G1 @ (x W1 + b1))
    sgemm(x, W1, Y, NN, HH, HH, b1, nullptr, 0, nullptr);
    convt_kernel<<<cvt_grid, cvt_blk>>>(Y, BtYh, BtYl, NN, HH);
    tgemm(G1, BtYh, BtYl, part, NN, NN, HH, nullptr, 4);
    reduce4_kernel<<<red_grid, 256>>>(part, h1, nullptr, 1, nullptr);

    // h2 = relu(G1 @ (h1 W2 + b2) + h1)
    sgemm(h1, W2, Y, NN, HH, HH, b2, nullptr, 0, nullptr);
    convt_kernel<<<cvt_grid, cvt_blk>>>(Y, BtYh, BtYl, NN, HH);
    tgemm(G1, BtYh, BtYl, part, NN, NN, HH, nullptr, 4);
    reduce4_kernel<<<red_grid, 256>>>(part, h2, h1, 1, nullptr);

    // h3_c1 -> fus[0]
    sgemm(h2, W3, Y, NN, HH, HH, b3, nullptr, 0, nullptr);
    convt_kernel<<<cvt_grid, cvt_blk>>>(Y, BtYh, BtYl, NN, HH);
    tgemm(G1, BtYh, BtYl, part, NN, NN, HH, nullptr, 4);
    reduce4_kernel<<<red_grid, 256>>>(part, fus, h2, 1, nullptr);

    // z1 = G1 @ (h1 W1h + b1h)
    sgemm(h1, W1h, Y, NN, HH, HH, b1h, nullptr, 0, nullptr);
    convt_kernel<<<cvt_grid, cvt_blk>>>(Y, BtYh, BtYl, NN, HH);
    tgemm(G1, BtYh, BtYl, part, NN, NN, HH, nullptr, 4);
    reduce4_kernel<<<red_grid, 256>>>(part, z1, nullptr, 0, nullptr);

    // z3 = G3 @ (h1 W3h + b3h)
    sgemm(h1, W3h, Y, NN, HH, HH, b3h, nullptr, 0, nullptr);
    convt_kernel<<<cvt_grid, cvt_blk>>>(Y, BtYh, BtYl, NN, HH);
    tgemm(G3, BtYh, BtYl, part, NN, NN, HH, nullptr, 4);
    reduce4_kernel<<<red_grid, 256>>>(part, z3, nullptr, 0, nullptr);

    // mixup (permuted-graph term == z[perm])
    mixcombine_kernel<<<(NN * HH + 255) / 256, 256>>>(z1, z3, perm, lam, mix);

    // MHA mix (nh=2): qkv = mix @ Wqkv^T + b   (Bt = WqkvM directly)
    convnt_kernel<<<(3 * HH * HH + 255) / 256, 256>>>(WqkvM, BtWh, BtWl, 3 * HH * HH);
    tgemm(mix, BtWh, BtWl, qkv, 2 * NN, HH, 3 * HH, bqkvM, 1);
    attn_kernel<<<(NN * 2 + 255) / 256, 256>>>(qkv, obar, 2);
    sgemm(obar, ToM, h1mix, NN, HH, HH, boM, nullptr, 0, nullptr);

    // h2_mix = relu(G1 @ (h1mix W2m + b2m) + h1mix)
    sgemm(h1mix, W2m, Y, NN, HH, HH, b2m, nullptr, 0, nullptr);
    convt_kernel<<<cvt_grid, cvt_blk>>>(Y, BtYh, BtYl, NN, HH);
    tgemm(G1, BtYh, BtYl, part, NN, NN, HH, nullptr, 4);
    reduce4_kernel<<<red_grid, 256>>>(part, h2, h1mix, 1, nullptr);

    // h3_c2 = relu(G1 @ (h2mix W3m + b3m) + h2mix) * beta -> fus[1]
    sgemm(h2, W3m, Y, NN, HH, HH, b3m, nullptr, 0, nullptr);
    convt_kernel<<<cvt_grid, cvt_blk>>>(Y, BtYh, BtYl, NN, HH);
    tgemm(G1, BtYh, BtYl, part, NN, NN, HH, nullptr, 4);
    reduce4_kernel<<<red_grid, 256>>>(part, fus + (size_t)NN * HH, h2, 1, beta);

    // MHA fus (nh=4)
    convnt_kernel<<<(3 * HH * HH + 255) / 256, 256>>>(WqkvF, BtWh, BtWl, 3 * HH * HH);
    tgemm(fus, BtWh, BtWl, qkv, 2 * NN, HH, 3 * HH, bqkvF, 1);
    attn_kernel<<<(NN * 4 + 255) / 256, 256>>>(qkv, obar, 4);
    sgemm(obar, ToF, h3, NN, HH, HH, boF, nullptr, 0, nullptr);

    // edge predictions
    edge_kernel<<<EE / 8, 256>>>(h3, ei, Wc, bc, out);
}